// round 2
// baseline (speedup 1.0000x reference)
#include <cuda_runtime.h>
#include <math.h>

#define DD 256      // D
#define EE 1024     // E
#define FF 1024     // F = 4*D
#define NROWS 4096  // N
#define ESPLIT 32
#define ECHUNK (EE / ESPLIT)   // 32
#define DT 16

typedef unsigned long long u64;

// ---- static scratch (no allocations allowed) ----
__device__ float g_w[EE * EE];                          // 4 MB: softmax gate weights
__device__ float g_part[(size_t)ESPLIT * DD * FF];      // 32 MB: split-K partials of W_eff
__device__ float g_bpart[ESPLIT * FF];                  // 128 KB: split-K partials of b_eff
__device__ float g_Weff[DD * FF];                       // 1 MB
__device__ float g_beff[FF];                            // 4 KB

// ---- packed fp32x2 helpers (FFMA2: only reachable via PTX) ----
__device__ __forceinline__ u64 pk2(float a, float b) {
    u64 r;
    asm("mov.b64 %0, {%1, %2};" : "=l"(r) : "f"(a), "f"(b));
    return r;
}
__device__ __forceinline__ u64 ffma2(u64 a, u64 b, u64 c) {
    u64 d;
    asm("fma.rn.f32x2 %0, %1, %2, %3;" : "=l"(d) : "l"(a), "l"(b), "l"(c));
    return d;
}
union U2 { u64 u; float2 f; };

// ============================================================
// Kernel 1: gate GEMM  g_w[i,j] = x[i,:] @ gate_W[:,j] + gate_b[j]
// i in [0,1024). 128x128 tile, BK=16, 256 threads, 8x8/thread, FFMA2.
// ============================================================
__global__ void gate_gemm(const float* __restrict__ x,
                          const float* __restrict__ gW,
                          const float* __restrict__ gb) {
    __shared__ __align__(16) float As[16][132];
    __shared__ __align__(16) float Bs[16][128];
    const int tid = threadIdx.x;
    const int i0 = blockIdx.y * 128;
    const int j0 = blockIdx.x * 128;
    const int tx = tid & 15;
    const int ty = tid >> 4;

    u64 acc2[8][4];
    const u64 z = pk2(0.f, 0.f);
#pragma unroll
    for (int r = 0; r < 8; r++)
#pragma unroll
        for (int c = 0; c < 4; c++) acc2[r][c] = z;

    for (int k0 = 0; k0 < DD; k0 += 16) {
#pragma unroll
        for (int t = 0; t < 2; t++) {
            int idx = tid + t * 256;
            int i = idx >> 2;
            int kc = (idx & 3) * 4;
            float4 v = *(const float4*)&x[(size_t)(i0 + i) * DD + k0 + kc];
            As[kc + 0][i] = v.x; As[kc + 1][i] = v.y;
            As[kc + 2][i] = v.z; As[kc + 3][i] = v.w;
        }
#pragma unroll
        for (int t = 0; t < 2; t++) {
            int idx = tid + t * 256;
            int r = idx >> 5;
            int c = (idx & 31) * 4;
            *(float4*)&Bs[r][c] = *(const float4*)&gW[(size_t)(k0 + r) * EE + j0 + c];
        }
        __syncthreads();
#pragma unroll
        for (int k = 0; k < 16; k++) {
            float a[8];
            *(float4*)&a[0] = *(const float4*)&As[k][ty * 8];
            *(float4*)&a[4] = *(const float4*)&As[k][ty * 8 + 4];
            u64 b2[4];
            const u64* bp = (const u64*)&Bs[k][tx * 8];
            b2[0] = bp[0]; b2[1] = bp[1]; b2[2] = bp[2]; b2[3] = bp[3];
#pragma unroll
            for (int r = 0; r < 8; r++) {
                u64 a2 = pk2(a[r], a[r]);
#pragma unroll
                for (int c = 0; c < 4; c++) acc2[r][c] = ffma2(a2, b2[c], acc2[r][c]);
            }
        }
        __syncthreads();
    }

    float bias[8];
#pragma unroll
    for (int c = 0; c < 8; c++) bias[c] = gb[j0 + tx * 8 + c];
#pragma unroll
    for (int r = 0; r < 8; r++) {
        int gi = i0 + ty * 8 + r;
        U2 t0, t1, t2, t3;
        t0.u = acc2[r][0]; t1.u = acc2[r][1]; t2.u = acc2[r][2]; t3.u = acc2[r][3];
        float4 v0, v1;
        v0.x = t0.f.x + bias[0]; v0.y = t0.f.y + bias[1];
        v0.z = t1.f.x + bias[2]; v0.w = t1.f.y + bias[3];
        v1.x = t2.f.x + bias[4]; v1.y = t2.f.y + bias[5];
        v1.z = t3.f.x + bias[6]; v1.w = t3.f.y + bias[7];
        *(float4*)&g_w[(size_t)gi * EE + j0 + tx * 8] = v0;
        *(float4*)&g_w[(size_t)gi * EE + j0 + tx * 8 + 4] = v1;
    }
}

// ============================================================
// Kernel 2: row softmax in-place on g_w (1024 rows x 1024)
// ============================================================
__global__ void softmax_rows() {
    const int row = blockIdx.x;
    const int tid = threadIdx.x;
    const int lane = tid & 31;
    const int wid = tid >> 5;
    float4* p = ((float4*)g_w) + (size_t)row * (EE / 4);
    float4 v = p[tid];

    __shared__ float red[8];
    __shared__ float bc;

    float m = fmaxf(fmaxf(v.x, v.y), fmaxf(v.z, v.w));
#pragma unroll
    for (int o = 16; o > 0; o >>= 1) m = fmaxf(m, __shfl_xor_sync(0xffffffffu, m, o));
    if (lane == 0) red[wid] = m;
    __syncthreads();
    if (tid == 0) {
        float t = red[0];
#pragma unroll
        for (int i = 1; i < 8; i++) t = fmaxf(t, red[i]);
        bc = t;
    }
    __syncthreads();
    m = bc;
    __syncthreads();

    v.x = expf(v.x - m); v.y = expf(v.y - m);
    v.z = expf(v.z - m); v.w = expf(v.w - m);
    float s = v.x + v.y + v.z + v.w;
#pragma unroll
    for (int o = 16; o > 0; o >>= 1) s += __shfl_xor_sync(0xffffffffu, s, o);
    if (lane == 0) red[wid] = s;
    __syncthreads();
    if (tid == 0) {
        float t = 0.f;
#pragma unroll
        for (int i = 0; i < 8; i++) t += red[i];
        bc = t;
    }
    __syncthreads();
    float inv = 1.f / bc;
    v.x *= inv; v.y *= inv; v.z *= inv; v.w *= inv;
    p[tid] = v;
}

// ============================================================
// Kernel 3: split-K W_eff partials (the HBM-bound stream) + b_eff
// partials folded into the blockIdx.x==0 CTAs.
// ============================================================
__global__ void weff_partial(const float* __restrict__ eW,
                             const float* __restrict__ eb) {
    const int tid = threadIdx.x;                  // f4 index
    const int d0 = blockIdx.x * DT;
    const int es = blockIdx.y;
    const int e0 = es * ECHUNK;
    const bool doB = (blockIdx.x == 0);

    float4 acc[DT];
#pragma unroll
    for (int i = 0; i < DT; i++) acc[i] = make_float4(0.f, 0.f, 0.f, 0.f);
    float4 bacc = make_float4(0.f, 0.f, 0.f, 0.f);

    const float4* wbase = ((const float4*)g_w) + (size_t)e0 * (FF / 4) + tid;
    const float4* ebase = ((const float4*)eW) + ((size_t)e0 * DD + d0) * (FF / 4) + tid;
    const float4* bbase = ((const float4*)eb) + (size_t)e0 * (FF / 4) + tid;

    for (int e = 0; e < ECHUNK; e++) {
        float4 wv = wbase[(size_t)e * (FF / 4)];
        if (doB) {
            float4 bv = __ldcs(bbase + (size_t)e * (FF / 4));
            bacc.x += wv.x * bv.x; bacc.y += wv.y * bv.y;
            bacc.z += wv.z * bv.z; bacc.w += wv.w * bv.w;
        }
        const float4* ep = ebase + (size_t)e * DD * (FF / 4);
#pragma unroll
        for (int dd = 0; dd < DT; dd++) {
            float4 ev = __ldcs(ep + (size_t)dd * (FF / 4));
            acc[dd].x += wv.x * ev.x;
            acc[dd].y += wv.y * ev.y;
            acc[dd].z += wv.z * ev.z;
            acc[dd].w += wv.w * ev.w;
        }
    }

    float4* outp = ((float4*)g_part) + ((size_t)es * DD + d0) * (FF / 4) + tid;
#pragma unroll
    for (int dd = 0; dd < DT; dd++) outp[(size_t)dd * (FF / 4)] = acc[dd];
    if (doB) ((float4*)g_bpart)[(size_t)es * (FF / 4) + tid] = bacc;
}

// ============================================================
// Kernel 4: deterministic fixed-order reduction of partials.
// ============================================================
__global__ void reduce_parts() {
    const int idx = blockIdx.x * blockDim.x + threadIdx.x;  // over D*F/4
    if (idx < DD * FF / 4) {
        float4 s = make_float4(0.f, 0.f, 0.f, 0.f);
#pragma unroll 4
        for (int p = 0; p < ESPLIT; p++) {
            float4 v = ((const float4*)g_part)[(size_t)p * (DD * FF / 4) + idx];
            s.x += v.x; s.y += v.y; s.z += v.z; s.w += v.w;
        }
        ((float4*)g_Weff)[idx] = s;
    }
    if (idx < FF / 4) {
        float4 s = make_float4(0.f, 0.f, 0.f, 0.f);
#pragma unroll 4
        for (int p = 0; p < ESPLIT; p++) {
            float4 v = ((const float4*)g_bpart)[(size_t)p * (FF / 4) + idx];
            s.x += v.x; s.y += v.y; s.z += v.z; s.w += v.w;
        }
        ((float4*)g_beff)[idx] = s;
    }
}

// ============================================================
// Kernel 5: final GEMM  out = x @ W_eff + b_eff
// M=4096, N=1024, K=256. 128x128 tile, BK=16, 256 thr, 8x8/thread, FFMA2.
// ============================================================
__global__ void final_gemm(const float* __restrict__ x, float* __restrict__ out) {
    __shared__ __align__(16) float As[16][132];
    __shared__ __align__(16) float Bs[16][128];
    const int tid = threadIdx.x;
    const int i0 = blockIdx.y * 128;
    const int j0 = blockIdx.x * 128;
    const int tx = tid & 15;
    const int ty = tid >> 4;

    u64 acc2[8][4];
    const u64 z = pk2(0.f, 0.f);
#pragma unroll
    for (int r = 0; r < 8; r++)
#pragma unroll
        for (int c = 0; c < 4; c++) acc2[r][c] = z;

    for (int k0 = 0; k0 < DD; k0 += 16) {
#pragma unroll
        for (int t = 0; t < 2; t++) {
            int idx = tid + t * 256;
            int i = idx >> 2;
            int kc = (idx & 3) * 4;
            float4 v = *(const float4*)&x[(size_t)(i0 + i) * DD + k0 + kc];
            As[kc + 0][i] = v.x; As[kc + 1][i] = v.y;
            As[kc + 2][i] = v.z; As[kc + 3][i] = v.w;
        }
#pragma unroll
        for (int t = 0; t < 2; t++) {
            int idx = tid + t * 256;
            int r = idx >> 5;
            int c = (idx & 31) * 4;
            *(float4*)&Bs[r][c] = *(const float4*)&g_Weff[(size_t)(k0 + r) * FF + j0 + c];
        }
        __syncthreads();
#pragma unroll
        for (int k = 0; k < 16; k++) {
            float a[8];
            *(float4*)&a[0] = *(const float4*)&As[k][ty * 8];
            *(float4*)&a[4] = *(const float4*)&As[k][ty * 8 + 4];
            u64 b2[4];
            const u64* bp = (const u64*)&Bs[k][tx * 8];
            b2[0] = bp[0]; b2[1] = bp[1]; b2[2] = bp[2]; b2[3] = bp[3];
#pragma unroll
            for (int r = 0; r < 8; r++) {
                u64 a2 = pk2(a[r], a[r]);
#pragma unroll
                for (int c = 0; c < 4; c++) acc2[r][c] = ffma2(a2, b2[c], acc2[r][c]);
            }
        }
        __syncthreads();
    }

    float bias[8];
#pragma unroll
    for (int c = 0; c < 8; c++) bias[c] = g_beff[j0 + tx * 8 + c];
#pragma unroll
    for (int r = 0; r < 8; r++) {
        int gi = i0 + ty * 8 + r;
        U2 t0, t1, t2, t3;
        t0.u = acc2[r][0]; t1.u = acc2[r][1]; t2.u = acc2[r][2]; t3.u = acc2[r][3];
        float4 v0, v1;
        v0.x = t0.f.x + bias[0]; v0.y = t0.f.y + bias[1];
        v0.z = t1.f.x + bias[2]; v0.w = t1.f.y + bias[3];
        v1.x = t2.f.x + bias[4]; v1.y = t2.f.y + bias[5];
        v1.z = t3.f.x + bias[6]; v1.w = t3.f.y + bias[7];
        *(float4*)&out[(size_t)gi * FF + j0 + tx * 8] = v0;
        *(float4*)&out[(size_t)gi * FF + j0 + tx * 8 + 4] = v1;
    }
}

// ============================================================
extern "C" void kernel_launch(void* const* d_in, const int* in_sizes, int n_in,
                              void* d_out, int out_size) {
    const float* x  = (const float*)d_in[0];   // (4096, 256)
    const float* gW = (const float*)d_in[1];   // (256, 1024)
    const float* gb = (const float*)d_in[2];   // (1024,)
    const float* eW = (const float*)d_in[3];   // (1024, 256, 1024)
    const float* eb = (const float*)d_in[4];   // (1024, 1024)
    float* out = (float*)d_out;                // (4096, 1024)

    gate_gemm<<<dim3(EE / 128, EE / 128), 256>>>(x, gW, gb);
    softmax_rows<<<EE, 256>>>();
    weff_partial<<<dim3(DD / DT, ESPLIT), 256>>>(eW, eb);
    reduce_parts<<<(DD * FF / 4) / 256, 256>>>();
    final_gemm<<<dim3(FF / 128, NROWS / 128), 256>>>(x, out);
}